// round 15
// baseline (speedup 1.0000x reference)
#include <cuda_runtime.h>
#include <cuda_fp16.h>
#include <cstdint>
#include <cstddef>

#define N_NODES 100000
#define N_EDGES 1600000
#define N_LBL   200000
#define DIM_IN  256
#define DIM_H1  128
#define DIM_H   64
#define DIM_EA  8

#define SCAN_TPB    512
#define SCAN_BLOCKS ((N_NODES + SCAN_TPB - 1) / SCAN_TPB)   // 196

// pre-split packed weights: uint32 = bf16x2 (b[2k2] low, b[2k2+1] high)
#define WOFF_W1  0
#define WOFF_W2  16384
#define WOFF_WG1 20480
#define WOFF_WG2 22528
#define WTOTAL   24576

// ---------------- scratch (no allocations allowed) ----------------
__device__ __align__(16) uint32_t g_h1h[(size_t)N_NODES * (DIM_H1 / 2)];
__device__ __align__(16) uint32_t g_h1l[(size_t)N_NODES * (DIM_H1 / 2)];
__device__ __align__(16) uint32_t g_hh [(size_t)N_NODES * (DIM_H / 2)];
__device__ __align__(16) uint32_t g_hl [(size_t)N_NODES * (DIM_H / 2)];
__device__ __align__(16) __half2  g_xw [(size_t)N_NODES * (DIM_H / 2)];
__device__ __align__(16) uint32_t g_Wh[WTOTAL];
__device__ __align__(16) uint32_t g_Wl[WTOTAL];
__device__ float g_pre_s[N_NODES];
__device__ float g_pre_d[N_NODES];
__device__ int   g_perm[N_EDGES];
__device__ int   g_deg[N_NODES];
__device__ int   g_start[N_NODES + 1];
__device__ int   g_cursor[N_NODES];
__device__ int   g_part[SCAN_BLOCKS];
__device__ float g_dinv[N_NODES];
__device__ float g_dinv2[N_NODES];
__device__ int   g_flag[2];

__device__ __forceinline__ float leaky(float v) {
    return v > 0.0f ? v : 0.01f * v;
}

__device__ __forceinline__ void split_pair(float x0, float x1, uint32_t& hi, uint32_t& lo) {
    uint32_t h;
    asm("cvt.rn.bf16x2.f32 %0, %1, %2;" : "=r"(h) : "f"(x1), "f"(x0));
    float h0 = __uint_as_float(h << 16);
    float h1 = __uint_as_float(h & 0xffff0000u);
    float r0 = x0 - h0;
    float r1 = x1 - h1;
    uint32_t l;
    asm("cvt.rn.bf16x2.f32 %0, %1, %2;" : "=r"(l) : "f"(r1), "f"(r0));
    hi = h; lo = l;
}

// ---------------- weight pre-split ----------------
__global__ void weight_convert_kernel(const float* __restrict__ W1,
                                      const float* __restrict__ W2,
                                      const float* __restrict__ Wg1,
                                      const float* __restrict__ Wg2) {
    int idx = blockIdx.x * blockDim.x + threadIdx.x;
    if (idx >= WTOTAL) return;
    const float* W;
    int k2, n, N;
    if (idx < WOFF_W2)        { W = W1;  int i = idx;             N = 128; k2 = i >> 7; n = i & 127; }
    else if (idx < WOFF_WG1)  { W = W2;  int i = idx - WOFF_W2;   N = 64;  k2 = i >> 6; n = i & 63; }
    else if (idx < WOFF_WG2)  { W = Wg1; int i = idx - WOFF_WG1;  N = 64;  k2 = i >> 6; n = i & 63; }
    else                      { W = Wg2; int i = idx - WOFF_WG2;  N = 64;  k2 = i >> 6; n = i & 63; }
    float w0 = W[(size_t)(2 * k2) * N + n];
    float w1 = W[(size_t)(2 * k2 + 1) * N + n];
    uint32_t h, l;
    split_pair(w0, w1, h, l);
    g_Wh[idx] = h;
    g_Wl[idx] = l;
}

// ---------------- prep / CSR build (unchanged) ----------------
__global__ void prep_kernel(const int* __restrict__ ei, const int* __restrict__ eli) {
    int nb = gridDim.x - 2;
    if ((int)blockIdx.x < nb) {
        int i = blockIdx.x * blockDim.x + threadIdx.x;
        if (i < N_NODES) g_deg[i] = 0;
        return;
    }
    const int* p = (blockIdx.x == nb) ? ei : eli;
    int slot = (blockIdx.x == nb) ? 0 : 1;
    __shared__ int anynz;
    if (threadIdx.x == 0) anynz = 0;
    __syncthreads();
    for (int i = threadIdx.x; i < 2048; i += blockDim.x) {
        if (p[2 * i + 1] != 0) anynz = 1;
    }
    __syncthreads();
    if (threadIdx.x == 0) g_flag[slot] = (anynz == 0) ? 1 : 0;
}

__global__ void deg_hist_kernel(const void* __restrict__ raw) {
    int i = blockIdx.x * blockDim.x + threadIdx.x;
    if (i >= N_EDGES / 4) return;
    if (g_flag[0]) {
        const longlong2* p = (const longlong2*)((const long long*)raw + N_EDGES);
        longlong2 a = p[2 * i], b = p[2 * i + 1];
        atomicAdd(&g_deg[(int)a.x], 1);
        atomicAdd(&g_deg[(int)a.y], 1);
        atomicAdd(&g_deg[(int)b.x], 1);
        atomicAdd(&g_deg[(int)b.y], 1);
    } else {
        const int4* p = (const int4*)((const int*)raw + N_EDGES);
        int4 v = p[i];
        atomicAdd(&g_deg[v.x], 1);
        atomicAdd(&g_deg[v.y], 1);
        atomicAdd(&g_deg[v.z], 1);
        atomicAdd(&g_deg[v.w], 1);
    }
}

__global__ void scan_partials_kernel() {
    __shared__ int sh[SCAN_TPB];
    int t = threadIdx.x;
    int i = blockIdx.x * SCAN_TPB + t;
    int v = (i < N_NODES) ? g_deg[i] : 0;
    sh[t] = v;
    __syncthreads();
    for (int off = SCAN_TPB / 2; off > 0; off >>= 1) {
        if (t < off) sh[t] += sh[t + off];
        __syncthreads();
    }
    if (t == 0) g_part[blockIdx.x] = sh[0];
}

__global__ void scan_top_kernel() {
    __shared__ int sh[256];
    int t = threadIdx.x;
    int v = (t < SCAN_BLOCKS) ? g_part[t] : 0;
    sh[t] = v;
    __syncthreads();
    for (int off = 1; off < 256; off <<= 1) {
        int x = (t >= off) ? sh[t - off] : 0;
        __syncthreads();
        sh[t] += x;
        __syncthreads();
    }
    if (t < SCAN_BLOCKS) g_part[t] = sh[t] - v;
}

__global__ void scan_final_kernel() {
    __shared__ int sh[SCAN_TPB];
    int t = threadIdx.x;
    int i = blockIdx.x * SCAN_TPB + t;
    int v = (i < N_NODES) ? g_deg[i] : 0;
    sh[t] = v;
    __syncthreads();
    for (int off = 1; off < SCAN_TPB; off <<= 1) {
        int x = (t >= off) ? sh[t - off] : 0;
        __syncthreads();
        sh[t] += x;
        __syncthreads();
    }
    if (i < N_NODES) {
        int excl = g_part[blockIdx.x] + sh[t] - v;
        g_start[i]  = excl;
        g_cursor[i] = excl;
        float fd = (float)(v + 1);
        g_dinv[i]  = rsqrtf(fd);
        g_dinv2[i] = 1.0f / fd;
    }
    if (i == 0) g_start[N_NODES] = N_EDGES;
}

__global__ void bucket_fill_kernel(const void* __restrict__ raw) {
    int e = blockIdx.x * blockDim.x + threadIdx.x;
    if (e >= N_EDGES) return;
    int r, c;
    if (g_flag[0]) {
        const long long* p = (const long long*)raw;
        r = (int)p[e];
        c = (int)p[N_EDGES + e];
    } else {
        const int* p = (const int*)raw;
        r = p[e];
        c = p[N_EDGES + e];
    }
    int pos = atomicAdd(&g_cursor[c], 1);
    g_perm[pos] = r;
}

// ---------------- BF16 tensor-core GEMM ----------------
__device__ __forceinline__ void mma_bf16(float* acc, const uint32_t* a, const uint32_t* b) {
    asm volatile(
        "mma.sync.aligned.m16n8k16.row.col.f32.bf16.bf16.f32 "
        "{%0,%1,%2,%3}, {%4,%5,%6,%7}, {%8,%9}, {%0,%1,%2,%3};"
        : "+f"(acc[0]), "+f"(acc[1]), "+f"(acc[2]), "+f"(acc[3])
        : "r"(a[0]), "r"(a[1]), "r"(a[2]), "r"(a[3]), "r"(b[0]), "r"(b[1]));
}

__device__ __forceinline__ void cp_async16(uint32_t dst, const void* src, int szbytes) {
    asm volatile("cp.async.cg.shared.global [%0], [%1], 16, %2;"
                 :: "r"(dst), "l"(src), "r"(szbytes));
}

// C[M,N] = act(A[M,K] @ B[K,N] + bias).  BM=128, BN=64, BK=16, 256 threads (8 warps, 4x2).
// PACKED_A: A given as k-pair-packed bf16x2 hi/lo [M][K/2] uint32 arrays.
// OMODE: 0 = fp32, 1 = half2 packed, 2 = bf16 hi/lo packed (C0=hi, C1=lo).
template<bool BIAS, bool ACT, bool PACKED_A, int OMODE>
__global__ __launch_bounds__(256) void bf16_gemm_kernel(
        const float* __restrict__ A,
        const uint32_t* __restrict__ Ahg, const uint32_t* __restrict__ Alg,
        const uint32_t* __restrict__ Bh, const uint32_t* __restrict__ Bl,
        const float* __restrict__ bias, void* __restrict__ C0, void* __restrict__ C1,
        int M, int N, int K) {
    constexpr int BM = 128, BK = 16;
    constexpr int ASTR  = 20;   // fp32 floats per row
    constexpr int ASTRP = 12;   // packed uint32 per row (12g+tig mod 32: conflict-free)
    constexpr int BSTR  = 72;
    constexpr size_t ABYTES = PACKED_A ? (size_t)2 * BM * ASTRP * 4 * 2
                                       : (size_t)2 * BM * ASTR * 4;
    constexpr size_t BH_OFF = ABYTES;
    constexpr size_t BL_OFF = ABYTES + (size_t)2 * 8 * BSTR * 4;
    __shared__ __align__(16) char sraw[BL_OFF + (size_t)2 * 8 * BSTR * 4];

    const int tid  = threadIdx.x;
    const int warp = tid >> 5, lane = tid & 31;
    const int g    = lane >> 2, tig = lane & 3;
    const int wm0  = (warp & 3) * 32;
    const int wn0  = (warp >> 2) * 32;
    const int row0 = blockIdx.y * BM;
    const int col0 = blockIdx.x * 64;

    const uint32_t sbase = (uint32_t)__cvta_generic_to_shared(sraw);

    // fp32-A loader coords
    const int ar0 = (tid * 4) >> 4,         ac0 = (tid * 4) & 15;
    const int ar1 = ((tid + 256) * 4) >> 4, ac1 = ((tid + 256) * 4) & 15;
    // packed-A loader coords: 256 float4 per plane, 1 hi + 1 lo per thread
    const int par = tid >> 1, pac = (tid & 1) * 4;
    // B loader coords
    const int bidx = (tid & 127) * 4;
    const int bk2 = bidx >> 6, bnn = bidx & 63;

    float acc[2][4][4];
#pragma unroll
    for (int mt = 0; mt < 2; mt++)
#pragma unroll
        for (int nt = 0; nt < 4; nt++)
#pragma unroll
            for (int i = 0; i < 4; i++) acc[mt][nt][i] = 0.0f;

    auto load_tile = [&](int k0, int st) {
        if (PACKED_A) {
            int sz = (row0 + par < M) ? 16 : 0;
            const uint32_t* sh = Ahg + (size_t)(row0 + par) * (K / 2) + (k0 >> 1) + pac;
            const uint32_t* sl = Alg + (size_t)(row0 + par) * (K / 2) + (k0 >> 1) + pac;
            if (!sz) { sh = Ahg; sl = Alg; }
            cp_async16(sbase + ((st * BM + par) * ASTRP + pac) * 4, sh, sz);
            cp_async16(sbase + (uint32_t)(2 * BM * ASTRP * 4)
                             + ((st * BM + par) * ASTRP + pac) * 4, sl, sz);
        } else {
            const float* s0 = A + (size_t)(row0 + ar0) * K + k0 + ac0;
            const float* s1 = A + (size_t)(row0 + ar1) * K + k0 + ac1;
            int sz0 = (row0 + ar0 < M) ? 16 : 0;
            int sz1 = (row0 + ar1 < M) ? 16 : 0;
            if (!sz0) s0 = A;
            if (!sz1) s1 = A;
            cp_async16(sbase + ((st * BM + ar0) * ASTR + ac0) * 4, s0, sz0);
            cp_async16(sbase + ((st * BM + ar1) * ASTR + ac1) * 4, s1, sz1);
        }
        const uint32_t* bsrc = (tid < 128 ? Bh : Bl)
                             + ((size_t)(k0 >> 1) + bk2) * N + col0 + bnn;
        uint32_t bdst = sbase + (uint32_t)(tid < 128 ? BH_OFF : BL_OFF)
                      + ((st * 8 + bk2) * BSTR + bnn) * 4;
        cp_async16(bdst, bsrc, 16);
        asm volatile("cp.async.commit_group;");
    };

    const int ntiles = K / BK;
    load_tile(0, 0);

    for (int t = 0; t < ntiles; t++) {
        const int st = t & 1;
        if (t + 1 < ntiles) {
            load_tile((t + 1) * BK, st ^ 1);
            asm volatile("cp.async.wait_group 1;");
        } else {
            asm volatile("cp.async.wait_group 0;");
        }
        __syncthreads();

        uint32_t ah[2][4], al[2][4];
        if (PACKED_A) {
            const uint32_t* Ahs = (const uint32_t*)sraw;
            const uint32_t* Als = (const uint32_t*)(sraw + 2 * BM * ASTRP * 4);
#pragma unroll
            for (int mt = 0; mt < 2; mt++) {
                int r = wm0 + mt * 16 + g;
                ah[mt][0] = Ahs[(st * BM + r) * ASTRP + tig];
                ah[mt][1] = Ahs[(st * BM + r + 8) * ASTRP + tig];
                ah[mt][2] = Ahs[(st * BM + r) * ASTRP + tig + 4];
                ah[mt][3] = Ahs[(st * BM + r + 8) * ASTRP + tig + 4];
                al[mt][0] = Als[(st * BM + r) * ASTRP + tig];
                al[mt][1] = Als[(st * BM + r + 8) * ASTRP + tig];
                al[mt][2] = Als[(st * BM + r) * ASTRP + tig + 4];
                al[mt][3] = Als[(st * BM + r + 8) * ASTRP + tig + 4];
            }
        } else {
            const float* As = (const float*)sraw;
            const int kk = 2 * tig;
#pragma unroll
            for (int mt = 0; mt < 2; mt++) {
                int r = wm0 + mt * 16 + g;
                float2 x;
                x = *(const float2*)&As[(st * BM + r) * ASTR + kk];
                split_pair(x.x, x.y, ah[mt][0], al[mt][0]);
                x = *(const float2*)&As[(st * BM + r + 8) * ASTR + kk];
                split_pair(x.x, x.y, ah[mt][1], al[mt][1]);
                x = *(const float2*)&As[(st * BM + r) * ASTR + kk + 8];
                split_pair(x.x, x.y, ah[mt][2], al[mt][2]);
                x = *(const float2*)&As[(st * BM + r + 8) * ASTR + kk + 8];
                split_pair(x.x, x.y, ah[mt][3], al[mt][3]);
            }
        }
        uint32_t bhf[4][2], blf[4][2];
        {
            const uint32_t* Bhs = (const uint32_t*)(sraw + BH_OFF);
            const uint32_t* Bls = (const uint32_t*)(sraw + BL_OFF);
#pragma unroll
            for (int nt = 0; nt < 4; nt++) {
                int c = wn0 + nt * 8 + g;
                bhf[nt][0] = Bhs[(st * 8 + tig) * BSTR + c];
                bhf[nt][1] = Bhs[(st * 8 + tig + 4) * BSTR + c];
                blf[nt][0] = Bls[(st * 8 + tig) * BSTR + c];
                blf[nt][1] = Bls[(st * 8 + tig + 4) * BSTR + c];
            }
        }
#pragma unroll
        for (int mt = 0; mt < 2; mt++)
#pragma unroll
            for (int nt = 0; nt < 4; nt++) {
                mma_bf16(acc[mt][nt], ah[mt], bhf[nt]);
                mma_bf16(acc[mt][nt], ah[mt], blf[nt]);
                mma_bf16(acc[mt][nt], al[mt], bhf[nt]);
            }
        __syncthreads();
    }

    // epilogue
#pragma unroll
    for (int mt = 0; mt < 2; mt++) {
#pragma unroll
        for (int nt = 0; nt < 4; nt++) {
            int r = row0 + wm0 + mt * 16 + g;
            int c = col0 + wn0 + nt * 8 + 2 * tig;   // always even
            float b0 = 0.f, b1 = 0.f;
            if (BIAS) { b0 = __ldg(&bias[c]); b1 = __ldg(&bias[c + 1]); }
#pragma unroll
            for (int half = 0; half < 2; half++) {
                int rr = r + half * 8;
                if (rr >= M) continue;
                float v0 = acc[mt][nt][2 * half + 0] + b0;
                float v1 = acc[mt][nt][2 * half + 1] + b1;
                if (ACT) { v0 = leaky(v0); v1 = leaky(v1); }
                if (OMODE == 0) {
                    *(float2*)((float*)C0 + (size_t)rr * N + c) = make_float2(v0, v1);
                } else if (OMODE == 1) {
                    ((__half2*)C0)[(size_t)rr * (N / 2) + c / 2] = __floats2half2_rn(v0, v1);
                } else {
                    uint32_t h, l;
                    split_pair(v0, v1, h, l);
                    ((uint32_t*)C0)[(size_t)rr * (N / 2) + c / 2] = h;
                    ((uint32_t*)C1)[(size_t)rr * (N / 2) + c / 2] = l;
                }
            }
        }
    }
}

// ---------------- fused GCN aggregation: one warp per destination node ----------------
// PROJ=false: write h packed bf16 hi/lo (feeds next GEMM). PROJ=true: write fp32 + head proj.
template<bool PROJ>
__global__ __launch_bounds__(256) void gcn_agg_kernel(const __half2* __restrict__ xw,
                                                      const float* __restrict__ bias,
                                                      float* __restrict__ hdst,
                                                      uint32_t* __restrict__ Hh,
                                                      uint32_t* __restrict__ Hl,
                                                      const float* __restrict__ Wp) {
    int node = blockIdx.x * (blockDim.x >> 5) + (threadIdx.x >> 5);
    int lane = threadIdx.x & 31;
    if (node >= N_NODES) return;

    int s   = g_start[node];
    int end = g_start[node + 1];
    float dcol = g_dinv[node];

    float ax = 0.0f, ay = 0.0f;
    int j = s;
    for (; j + 4 <= end; j += 4) {
        int r0 = g_perm[j];
        int r1 = g_perm[j + 1];
        int r2 = g_perm[j + 2];
        int r3 = g_perm[j + 3];
        float w0 = g_dinv[r0] * dcol;
        float w1 = g_dinv[r1] * dcol;
        float w2 = g_dinv[r2] * dcol;
        float w3 = g_dinv[r3] * dcol;
        float2 f0 = __half22float2(xw[(size_t)r0 * 32 + lane]);
        float2 f1 = __half22float2(xw[(size_t)r1 * 32 + lane]);
        float2 f2 = __half22float2(xw[(size_t)r2 * 32 + lane]);
        float2 f3 = __half22float2(xw[(size_t)r3 * 32 + lane]);
        ax = fmaf(w0, f0.x, ax); ay = fmaf(w0, f0.y, ay);
        ax = fmaf(w1, f1.x, ax); ay = fmaf(w1, f1.y, ay);
        ax = fmaf(w2, f2.x, ax); ay = fmaf(w2, f2.y, ay);
        ax = fmaf(w3, f3.x, ax); ay = fmaf(w3, f3.y, ay);
    }
    for (; j < end; j++) {
        int r0 = g_perm[j];
        float w0 = g_dinv[r0] * dcol;
        float2 f0 = __half22float2(xw[(size_t)r0 * 32 + lane]);
        ax = fmaf(w0, f0.x, ax);
        ay = fmaf(w0, f0.y, ay);
    }
    float sw = g_dinv2[node];
    float2 fs = __half22float2(xw[(size_t)node * 32 + lane]);
    ax = fmaf(sw, fs.x, ax);
    ay = fmaf(sw, fs.y, ay);

    ax = leaky(ax + bias[2 * lane]);
    ay = leaky(ay + bias[2 * lane + 1]);

    if (PROJ) {
        *(float2*)(hdst + (size_t)node * DIM_H + 2 * lane) = make_float2(ax, ay);
        float2 ws = *(const float2*)(Wp + 2 * lane);
        float2 wd = *(const float2*)(Wp + DIM_H + 2 * lane);
        float ps = ax * ws.x + ay * ws.y;
        float pd = ax * wd.x + ay * wd.y;
#pragma unroll
        for (int o = 16; o; o >>= 1) {
            ps += __shfl_xor_sync(0xffffffffu, ps, o);
            pd += __shfl_xor_sync(0xffffffffu, pd, o);
        }
        if (lane == 0) {
            g_pre_s[node] = ps;
            g_pre_d[node] = pd;
        }
    } else {
        uint32_t h, l;
        split_pair(ax, ay, h, l);
        Hh[(size_t)node * 32 + lane] = h;
        Hl[(size_t)node * 32 + lane] = l;
    }
}

// ---------------- edge scoring head: one THREAD per label edge ----------------
__global__ __launch_bounds__(256) void edge_score_kernel(
        const void* __restrict__ eli, const float* __restrict__ ea,
        const float* __restrict__ Wp, const float* __restrict__ bp,
        float* __restrict__ out) {
    int e = blockIdx.x * blockDim.x + threadIdx.x;
    if (e >= N_LBL) return;
    int s, d;
    if (g_flag[1]) {
        const long long* p = (const long long*)eli;
        s = (int)p[e];
        d = (int)p[N_LBL + e];
    } else {
        const int* p = (const int*)eli;
        s = p[e];
        d = p[N_LBL + e];
    }
    float4 a0 = *(const float4*)(ea + (size_t)e * DIM_EA);
    float4 a1 = *(const float4*)(ea + (size_t)e * DIM_EA + 4);
    float acc = g_pre_s[s] + g_pre_d[d] + __ldg(&bp[0]);
    acc += a0.x * __ldg(&Wp[128]) + a0.y * __ldg(&Wp[129])
         + a0.z * __ldg(&Wp[130]) + a0.w * __ldg(&Wp[131])
         + a1.x * __ldg(&Wp[132]) + a1.y * __ldg(&Wp[133])
         + a1.z * __ldg(&Wp[134]) + a1.w * __ldg(&Wp[135]);
    out[e] = acc;
}

// ---------------- host ----------------
static void* sym_addr(const void* sym) {
    void* p = nullptr;
    cudaGetSymbolAddress(&p, sym);
    return p;
}

extern "C" void kernel_launch(void* const* d_in, const int* in_sizes, int n_in,
                              void* d_out, int out_size) {
    static cudaStream_t s_prep = nullptr;
    static cudaEvent_t ev_fork = nullptr, ev_join = nullptr;
    if (s_prep == nullptr) {
        cudaStreamCreateWithFlags(&s_prep, cudaStreamNonBlocking);
        cudaEventCreateWithFlags(&ev_fork, cudaEventDisableTiming);
        cudaEventCreateWithFlags(&ev_join, cudaEventDisableTiming);
    }

    const float* x   = (const float*)d_in[0];
    const void*  ei  = d_in[1];
    const void*  eli = d_in[2];
    const float* ea  = (const float*)d_in[3];
    const float* W1  = (const float*)d_in[4];
    const float* b1  = (const float*)d_in[5];
    const float* W2  = (const float*)d_in[6];
    const float* b2  = (const float*)d_in[7];
    const float* Wg1 = (const float*)d_in[8];
    const float* bg1 = (const float*)d_in[9];
    const float* Wg2 = (const float*)d_in[10];
    const float* bg2 = (const float*)d_in[11];
    const float* Wp  = (const float*)d_in[12];
    const float* bp  = (const float*)d_in[13];

    float* out  = (float*)d_out;
    float* hout = out + N_LBL;

    uint32_t* h1h = (uint32_t*)sym_addr(g_h1h);
    uint32_t* h1l = (uint32_t*)sym_addr(g_h1l);
    uint32_t* hh  = (uint32_t*)sym_addr(g_hh);
    uint32_t* hl  = (uint32_t*)sym_addr(g_hl);
    __half2*  xw  = (__half2*)sym_addr(g_xw);
    uint32_t* Wh  = (uint32_t*)sym_addr(g_Wh);
    uint32_t* Wl  = (uint32_t*)sym_addr(g_Wl);

    // --- fork: CSR build on side stream ---
    cudaEventRecord(ev_fork, 0);
    cudaStreamWaitEvent(s_prep, ev_fork, 0);

    const int zero_blocks = (N_NODES + 255) / 256;
    // interleave host issuance so the ncu -s window lands on the big GEMMs
    prep_kernel<<<zero_blocks + 2, 256, 0, s_prep>>>((const int*)ei, (const int*)eli);
    deg_hist_kernel<<<(N_EDGES / 4 + 255) / 256, 256, 0, s_prep>>>(ei);
    scan_partials_kernel<<<SCAN_BLOCKS, SCAN_TPB, 0, s_prep>>>();

    const int gy = (N_NODES + 127) / 128;
    weight_convert_kernel<<<(WTOTAL + 255) / 256, 256>>>(W1, W2, Wg1, Wg2);
    bf16_gemm_kernel<true, true, false, 2><<<dim3(DIM_H1 / 64, gy), 256>>>(
        x, nullptr, nullptr, Wh + WOFF_W1, Wl + WOFF_W1, b1, h1h, h1l, N_NODES, DIM_H1, DIM_IN);
    bf16_gemm_kernel<true, true, true, 2><<<dim3(DIM_H / 64, gy), 256>>>(
        nullptr, h1h, h1l, Wh + WOFF_W2, Wl + WOFF_W2, b2, hh, hl, N_NODES, DIM_H, DIM_H1);

    scan_top_kernel<<<1, 256, 0, s_prep>>>();
    scan_final_kernel<<<SCAN_BLOCKS, SCAN_TPB, 0, s_prep>>>();
    bucket_fill_kernel<<<(N_EDGES + 255) / 256, 256, 0, s_prep>>>(ei);
    cudaEventRecord(ev_join, s_prep);

    const int agg_blocks = (N_NODES + 7) / 8;

    // --- GCN layer 1 ---
    bf16_gemm_kernel<false, false, true, 1><<<dim3(DIM_H / 64, gy), 256>>>(
        nullptr, hh, hl, Wh + WOFF_WG1, Wl + WOFF_WG1, nullptr, xw, nullptr, N_NODES, DIM_H, DIM_H);
    cudaStreamWaitEvent(0, ev_join, 0);
    gcn_agg_kernel<false><<<agg_blocks, 256>>>(xw, bg1, nullptr, hh, hl, nullptr);

    // --- GCN layer 2 (epilogue also computes head projections) ---
    bf16_gemm_kernel<false, false, true, 1><<<dim3(DIM_H / 64, gy), 256>>>(
        nullptr, hh, hl, Wh + WOFF_WG2, Wl + WOFF_WG2, nullptr, xw, nullptr, N_NODES, DIM_H, DIM_H);
    gcn_agg_kernel<true><<<agg_blocks, 256>>>(xw, bg2, hout, nullptr, nullptr, Wp);

    // --- edge scoring head: one thread per edge ---
    edge_score_kernel<<<(N_LBL + 255) / 256, 256>>>(eli, ea, Wp, bp, out);
}

// round 16
// speedup vs baseline: 1.0981x; 1.0981x over previous
#include <cuda_runtime.h>
#include <cuda_fp16.h>
#include <cstdint>
#include <cstddef>

#define N_NODES 100000
#define N_EDGES 1600000
#define N_LBL   200000
#define DIM_IN  256
#define DIM_H1  128
#define DIM_H   64
#define DIM_EA  8

#define SCAN_TPB    512
#define SCAN_BLOCKS ((N_NODES + SCAN_TPB - 1) / SCAN_TPB)   // 196

// pre-split packed weights: uint32 = bf16x2 (b[2k2] low, b[2k2+1] high)
#define WOFF_W1  0
#define WOFF_W2  16384
#define WOFF_WG1 20480
#define WOFF_WG2 22528
#define WTOTAL   24576

// ---------------- scratch (no allocations allowed) ----------------
__device__ __align__(16) float   g_h1[(size_t)N_NODES * DIM_H1];
__device__ __align__(16) float   g_h [(size_t)N_NODES * DIM_H];
__device__ __align__(16) __half2 g_xw[(size_t)N_NODES * (DIM_H / 2)];
__device__ __align__(16) uint32_t g_Wh[WTOTAL];
__device__ __align__(16) uint32_t g_Wl[WTOTAL];
__device__ float g_pre_s[N_NODES];
__device__ float g_pre_d[N_NODES];
__device__ int   g_perm[N_EDGES];
__device__ int   g_deg[N_NODES];
__device__ int   g_start[N_NODES + 1];
__device__ int   g_cursor[N_NODES];
__device__ int   g_part[SCAN_BLOCKS];
__device__ float g_dinv[N_NODES];
__device__ float g_dinv2[N_NODES];
__device__ int   g_flag[2];

__device__ __forceinline__ float leaky(float v) {
    return v > 0.0f ? v : 0.01f * v;
}

__device__ __forceinline__ void split_pair(float x0, float x1, uint32_t& hi, uint32_t& lo) {
    uint32_t h;
    asm("cvt.rn.bf16x2.f32 %0, %1, %2;" : "=r"(h) : "f"(x1), "f"(x0));
    float h0 = __uint_as_float(h << 16);
    float h1 = __uint_as_float(h & 0xffff0000u);
    float r0 = x0 - h0;
    float r1 = x1 - h1;
    uint32_t l;
    asm("cvt.rn.bf16x2.f32 %0, %1, %2;" : "=r"(l) : "f"(r1), "f"(r0));
    hi = h; lo = l;
}

// ---------------- weight pre-split: once per launch, ~2us ----------------
__global__ void weight_convert_kernel(const float* __restrict__ W1,
                                      const float* __restrict__ W2,
                                      const float* __restrict__ Wg1,
                                      const float* __restrict__ Wg2) {
    int idx = blockIdx.x * blockDim.x + threadIdx.x;
    if (idx >= WTOTAL) return;
    const float* W;
    int k2, n, N;
    if (idx < WOFF_W2)        { W = W1;  int i = idx;             N = 128; k2 = i >> 7; n = i & 127; }
    else if (idx < WOFF_WG1)  { W = W2;  int i = idx - WOFF_W2;   N = 64;  k2 = i >> 6; n = i & 63; }
    else if (idx < WOFF_WG2)  { W = Wg1; int i = idx - WOFF_WG1;  N = 64;  k2 = i >> 6; n = i & 63; }
    else                      { W = Wg2; int i = idx - WOFF_WG2;  N = 64;  k2 = i >> 6; n = i & 63; }
    float w0 = W[(size_t)(2 * k2) * N + n];
    float w1 = W[(size_t)(2 * k2 + 1) * N + n];
    uint32_t h, l;
    split_pair(w0, w1, h, l);
    g_Wh[idx] = h;
    g_Wl[idx] = l;
}

// ---------------- prep: zero deg + detect int64-ness of both index buffers ----------
__global__ void prep_kernel(const int* __restrict__ ei, const int* __restrict__ eli) {
    int nb = gridDim.x - 2;
    if ((int)blockIdx.x < nb) {
        int i = blockIdx.x * blockDim.x + threadIdx.x;
        if (i < N_NODES) g_deg[i] = 0;
        return;
    }
    const int* p = (blockIdx.x == nb) ? ei : eli;
    int slot = (blockIdx.x == nb) ? 0 : 1;
    __shared__ int anynz;
    if (threadIdx.x == 0) anynz = 0;
    __syncthreads();
    for (int i = threadIdx.x; i < 2048; i += blockDim.x) {
        if (p[2 * i + 1] != 0) anynz = 1;
    }
    __syncthreads();
    if (threadIdx.x == 0) g_flag[slot] = (anynz == 0) ? 1 : 0;
}

__global__ void deg_hist_kernel(const void* __restrict__ raw) {
    int i = blockIdx.x * blockDim.x + threadIdx.x;
    if (i >= N_EDGES / 4) return;
    if (g_flag[0]) {
        const longlong2* p = (const longlong2*)((const long long*)raw + N_EDGES);
        longlong2 a = p[2 * i], b = p[2 * i + 1];
        atomicAdd(&g_deg[(int)a.x], 1);
        atomicAdd(&g_deg[(int)a.y], 1);
        atomicAdd(&g_deg[(int)b.x], 1);
        atomicAdd(&g_deg[(int)b.y], 1);
    } else {
        const int4* p = (const int4*)((const int*)raw + N_EDGES);
        int4 v = p[i];
        atomicAdd(&g_deg[v.x], 1);
        atomicAdd(&g_deg[v.y], 1);
        atomicAdd(&g_deg[v.z], 1);
        atomicAdd(&g_deg[v.w], 1);
    }
}

__global__ void scan_partials_kernel() {
    __shared__ int sh[SCAN_TPB];
    int t = threadIdx.x;
    int i = blockIdx.x * SCAN_TPB + t;
    int v = (i < N_NODES) ? g_deg[i] : 0;
    sh[t] = v;
    __syncthreads();
    for (int off = SCAN_TPB / 2; off > 0; off >>= 1) {
        if (t < off) sh[t] += sh[t + off];
        __syncthreads();
    }
    if (t == 0) g_part[blockIdx.x] = sh[0];
}

__global__ void scan_top_kernel() {
    __shared__ int sh[256];
    int t = threadIdx.x;
    int v = (t < SCAN_BLOCKS) ? g_part[t] : 0;
    sh[t] = v;
    __syncthreads();
    for (int off = 1; off < 256; off <<= 1) {
        int x = (t >= off) ? sh[t - off] : 0;
        __syncthreads();
        sh[t] += x;
        __syncthreads();
    }
    if (t < SCAN_BLOCKS) g_part[t] = sh[t] - v;
}

__global__ void scan_final_kernel() {
    __shared__ int sh[SCAN_TPB];
    int t = threadIdx.x;
    int i = blockIdx.x * SCAN_TPB + t;
    int v = (i < N_NODES) ? g_deg[i] : 0;
    sh[t] = v;
    __syncthreads();
    for (int off = 1; off < SCAN_TPB; off <<= 1) {
        int x = (t >= off) ? sh[t - off] : 0;
        __syncthreads();
        sh[t] += x;
        __syncthreads();
    }
    if (i < N_NODES) {
        int excl = g_part[blockIdx.x] + sh[t] - v;
        g_start[i]  = excl;
        g_cursor[i] = excl;
        float fd = (float)(v + 1);
        g_dinv[i]  = rsqrtf(fd);
        g_dinv2[i] = 1.0f / fd;
    }
    if (i == 0) g_start[N_NODES] = N_EDGES;
}

__global__ void bucket_fill_kernel(const void* __restrict__ raw) {
    int e = blockIdx.x * blockDim.x + threadIdx.x;
    if (e >= N_EDGES) return;
    int r, c;
    if (g_flag[0]) {
        const long long* p = (const long long*)raw;
        r = (int)p[e];
        c = (int)p[N_EDGES + e];
    } else {
        const int* p = (const int*)raw;
        r = p[e];
        c = p[N_EDGES + e];
    }
    int pos = atomicAdd(&g_cursor[c], 1);
    g_perm[pos] = r;
}

// ---------------- BF16 tensor-core GEMM, pre-split B, cp.async double buffer -------
// (exact Round-14 proven version)
__device__ __forceinline__ void mma_bf16(float* acc, const uint32_t* a, const uint32_t* b) {
    asm volatile(
        "mma.sync.aligned.m16n8k16.row.col.f32.bf16.bf16.f32 "
        "{%0,%1,%2,%3}, {%4,%5,%6,%7}, {%8,%9}, {%0,%1,%2,%3};"
        : "+f"(acc[0]), "+f"(acc[1]), "+f"(acc[2]), "+f"(acc[3])
        : "r"(a[0]), "r"(a[1]), "r"(a[2]), "r"(a[3]), "r"(b[0]), "r"(b[1]));
}

__device__ __forceinline__ void cp_async16(uint32_t dst, const void* src, int szbytes) {
    asm volatile("cp.async.cg.shared.global [%0], [%1], 16, %2;"
                 :: "r"(dst), "l"(src), "r"(szbytes));
}

template<bool BIAS, bool ACT, bool HALF_OUT>
__global__ __launch_bounds__(256) void bf16_gemm_kernel(
        const float* __restrict__ A,
        const uint32_t* __restrict__ Bh, const uint32_t* __restrict__ Bl,
        const float* __restrict__ bias, void* __restrict__ Cout,
        int M, int N, int K) {
    constexpr int BM = 128, BK = 16;
    constexpr int ASTR = BK + 4;   // 20
    constexpr int BSTR = 64 + 8;   // 72
    __shared__ float    As[2][BM][ASTR];
    __shared__ uint32_t Bhs[2][8][BSTR];
    __shared__ uint32_t Bls[2][8][BSTR];

    const int tid  = threadIdx.x;
    const int warp = tid >> 5, lane = tid & 31;
    const int g    = lane >> 2, tig = lane & 3;
    const int wm0  = (warp & 3) * 32;
    const int wn0  = (warp >> 2) * 32;
    const int row0 = blockIdx.y * BM;
    const int col0 = blockIdx.x * 64;

    const int ar0 = (tid * 4) >> 4,         ac0 = (tid * 4) & 15;
    const int ar1 = ((tid + 256) * 4) >> 4, ac1 = ((tid + 256) * 4) & 15;
    const int bidx = (tid & 127) * 4;
    const int bk2 = bidx >> 6, bnn = bidx & 63;

    const uint32_t as_base  = (uint32_t)__cvta_generic_to_shared(&As[0][0][0]);
    const uint32_t bhs_base = (uint32_t)__cvta_generic_to_shared(&Bhs[0][0][0]);
    const uint32_t bls_base = (uint32_t)__cvta_generic_to_shared(&Bls[0][0][0]);

    float acc[2][4][4];
#pragma unroll
    for (int mt = 0; mt < 2; mt++)
#pragma unroll
        for (int nt = 0; nt < 4; nt++)
#pragma unroll
            for (int i = 0; i < 4; i++) acc[mt][nt][i] = 0.0f;

    auto load_tile = [&](int k0, int st) {
        const float* srcA0 = A + (size_t)(row0 + ar0) * K + k0 + ac0;
        const float* srcA1 = A + (size_t)(row0 + ar1) * K + k0 + ac1;
        int sz0 = (row0 + ar0 < M) ? 16 : 0;
        int sz1 = (row0 + ar1 < M) ? 16 : 0;
        if (!sz0) srcA0 = A;
        if (!sz1) srcA1 = A;
        cp_async16(as_base + ((st * BM + ar0) * ASTR + ac0) * 4, srcA0, sz0);
        cp_async16(as_base + ((st * BM + ar1) * ASTR + ac1) * 4, srcA1, sz1);
        const uint32_t* bsrc = (tid < 128 ? Bh : Bl)
                             + ((size_t)(k0 >> 1) + bk2) * N + col0 + bnn;
        uint32_t bdst = (tid < 128 ? bhs_base : bls_base)
                      + ((st * 8 + bk2) * BSTR + bnn) * 4;
        cp_async16(bdst, bsrc, 16);
        asm volatile("cp.async.commit_group;");
    };

    const int ntiles = K / BK;
    load_tile(0, 0);

    for (int t = 0; t < ntiles; t++) {
        const int st = t & 1;
        if (t + 1 < ntiles) {
            load_tile((t + 1) * BK, st ^ 1);
            asm volatile("cp.async.wait_group 1;");
        } else {
            asm volatile("cp.async.wait_group 0;");
        }
        __syncthreads();

        const int kk = 2 * tig;
        uint32_t ah[2][4], al[2][4];
#pragma unroll
        for (int mt = 0; mt < 2; mt++) {
            int r = wm0 + mt * 16 + g;
            float2 x;
            x = *(const float2*)&As[st][r][kk];
            split_pair(x.x, x.y, ah[mt][0], al[mt][0]);
            x = *(const float2*)&As[st][r + 8][kk];
            split_pair(x.x, x.y, ah[mt][1], al[mt][1]);
            x = *(const float2*)&As[st][r][kk + 8];
            split_pair(x.x, x.y, ah[mt][2], al[mt][2]);
            x = *(const float2*)&As[st][r + 8][kk + 8];
            split_pair(x.x, x.y, ah[mt][3], al[mt][3]);
        }
        uint32_t bh[4][2], bl[4][2];
#pragma unroll
        for (int nt = 0; nt < 4; nt++) {
            int c = wn0 + nt * 8 + g;
            bh[nt][0] = Bhs[st][tig][c];
            bh[nt][1] = Bhs[st][tig + 4][c];
            bl[nt][0] = Bls[st][tig][c];
            bl[nt][1] = Bls[st][tig + 4][c];
        }
#pragma unroll
        for (int mt = 0; mt < 2; mt++)
#pragma unroll
            for (int nt = 0; nt < 4; nt++) {
                mma_bf16(acc[mt][nt], ah[mt], bh[nt]);
                mma_bf16(acc[mt][nt], ah[mt], bl[nt]);
                mma_bf16(acc[mt][nt], al[mt], bh[nt]);
            }
        __syncthreads();
    }

#pragma unroll
    for (int mt = 0; mt < 2; mt++) {
#pragma unroll
        for (int nt = 0; nt < 4; nt++) {
            int r = row0 + wm0 + mt * 16 + g;
            int c = col0 + wn0 + nt * 8 + 2 * tig;
            float b0 = 0.f, b1 = 0.f;
            if (BIAS) { b0 = __ldg(&bias[c]); b1 = __ldg(&bias[c + 1]); }
            if (r < M) {
                float v0 = acc[mt][nt][0] + b0;
                float v1 = acc[mt][nt][1] + b1;
                if (ACT) { v0 = leaky(v0); v1 = leaky(v1); }
                if (HALF_OUT)
                    ((__half2*)Cout)[(size_t)r * (N / 2) + c / 2] = __floats2half2_rn(v0, v1);
                else
                    *(float2*)((float*)Cout + (size_t)r * N + c) = make_float2(v0, v1);
            }
            if (r + 8 < M) {
                float v2 = acc[mt][nt][2] + b0;
                float v3 = acc[mt][nt][3] + b1;
                if (ACT) { v2 = leaky(v2); v3 = leaky(v3); }
                if (HALF_OUT)
                    ((__half2*)Cout)[(size_t)(r + 8) * (N / 2) + c / 2] = __floats2half2_rn(v2, v3);
                else
                    *(float2*)((float*)Cout + (size_t)(r + 8) * N + c) = make_float2(v2, v3);
            }
        }
    }
}

// ---------------- fused GCN aggregation: one warp per destination node ----------------
template<bool PROJ>
__global__ __launch_bounds__(256) void gcn_agg_kernel(const __half2* __restrict__ xw,
                                                      const float* __restrict__ bias,
                                                      float* __restrict__ hdst,
                                                      const float* __restrict__ Wp) {
    int node = blockIdx.x * (blockDim.x >> 5) + (threadIdx.x >> 5);
    int lane = threadIdx.x & 31;
    if (node >= N_NODES) return;

    int s   = g_start[node];
    int end = g_start[node + 1];
    float dcol = g_dinv[node];

    float ax = 0.0f, ay = 0.0f;
    int j = s;
    for (; j + 4 <= end; j += 4) {
        int r0 = g_perm[j];
        int r1 = g_perm[j + 1];
        int r2 = g_perm[j + 2];
        int r3 = g_perm[j + 3];
        float w0 = g_dinv[r0] * dcol;
        float w1 = g_dinv[r1] * dcol;
        float w2 = g_dinv[r2] * dcol;
        float w3 = g_dinv[r3] * dcol;
        float2 f0 = __half22float2(xw[(size_t)r0 * 32 + lane]);
        float2 f1 = __half22float2(xw[(size_t)r1 * 32 + lane]);
        float2 f2 = __half22float2(xw[(size_t)r2 * 32 + lane]);
        float2 f3 = __half22float2(xw[(size_t)r3 * 32 + lane]);
        ax = fmaf(w0, f0.x, ax); ay = fmaf(w0, f0.y, ay);
        ax = fmaf(w1, f1.x, ax); ay = fmaf(w1, f1.y, ay);
        ax = fmaf(w2, f2.x, ax); ay = fmaf(w2, f2.y, ay);
        ax = fmaf(w3, f3.x, ax); ay = fmaf(w3, f3.y, ay);
    }
    for (; j < end; j++) {
        int r0 = g_perm[j];
        float w0 = g_dinv[r0] * dcol;
        float2 f0 = __half22float2(xw[(size_t)r0 * 32 + lane]);
        ax = fmaf(w0, f0.x, ax);
        ay = fmaf(w0, f0.y, ay);
    }
    float sw = g_dinv2[node];
    float2 fs = __half22float2(xw[(size_t)node * 32 + lane]);
    ax = fmaf(sw, fs.x, ax);
    ay = fmaf(sw, fs.y, ay);

    ax = leaky(ax + bias[2 * lane]);
    ay = leaky(ay + bias[2 * lane + 1]);
    *(float2*)(hdst + (size_t)node * DIM_H + 2 * lane) = make_float2(ax, ay);

    if (PROJ) {
        float2 ws = *(const float2*)(Wp + 2 * lane);
        float2 wd = *(const float2*)(Wp + DIM_H + 2 * lane);
        float ps = ax * ws.x + ay * ws.y;
        float pd = ax * wd.x + ay * wd.y;
#pragma unroll
        for (int o = 16; o; o >>= 1) {
            ps += __shfl_xor_sync(0xffffffffu, ps, o);
            pd += __shfl_xor_sync(0xffffffffu, pd, o);
        }
        if (lane == 0) {
            g_pre_s[node] = ps;
            g_pre_d[node] = pd;
        }
    }
}

// ---------------- edge scoring head: one THREAD per label edge ----------------
__global__ __launch_bounds__(256) void edge_score_kernel(
        const void* __restrict__ eli, const float* __restrict__ ea,
        const float* __restrict__ Wp, const float* __restrict__ bp,
        float* __restrict__ out) {
    int e = blockIdx.x * blockDim.x + threadIdx.x;
    if (e >= N_LBL) return;
    int s, d;
    if (g_flag[1]) {
        const long long* p = (const long long*)eli;
        s = (int)p[e];
        d = (int)p[N_LBL + e];
    } else {
        const int* p = (const int*)eli;
        s = p[e];
        d = p[N_LBL + e];
    }
    float4 a0 = *(const float4*)(ea + (size_t)e * DIM_EA);
    float4 a1 = *(const float4*)(ea + (size_t)e * DIM_EA + 4);
    float acc = g_pre_s[s] + g_pre_d[d] + __ldg(&bp[0]);
    acc += a0.x * __ldg(&Wp[128]) + a0.y * __ldg(&Wp[129])
         + a0.z * __ldg(&Wp[130]) + a0.w * __ldg(&Wp[131])
         + a1.x * __ldg(&Wp[132]) + a1.y * __ldg(&Wp[133])
         + a1.z * __ldg(&Wp[134]) + a1.w * __ldg(&Wp[135]);
    out[e] = acc;
}

// ---------------- host ----------------
static void* sym_addr(const void* sym) {
    void* p = nullptr;
    cudaGetSymbolAddress(&p, sym);
    return p;
}

extern "C" void kernel_launch(void* const* d_in, const int* in_sizes, int n_in,
                              void* d_out, int out_size) {
    static cudaStream_t s_prep = nullptr, s_w = nullptr;
    static cudaEvent_t ev_fork = nullptr, ev_join = nullptr, ev_w = nullptr;
    if (s_prep == nullptr) {
        cudaStreamCreateWithFlags(&s_prep, cudaStreamNonBlocking);
        cudaStreamCreateWithFlags(&s_w, cudaStreamNonBlocking);
        cudaEventCreateWithFlags(&ev_fork, cudaEventDisableTiming);
        cudaEventCreateWithFlags(&ev_join, cudaEventDisableTiming);
        cudaEventCreateWithFlags(&ev_w, cudaEventDisableTiming);
    }

    const float* x   = (const float*)d_in[0];
    const void*  ei  = d_in[1];
    const void*  eli = d_in[2];
    const float* ea  = (const float*)d_in[3];
    const float* W1  = (const float*)d_in[4];
    const float* b1  = (const float*)d_in[5];
    const float* W2  = (const float*)d_in[6];
    const float* b2  = (const float*)d_in[7];
    const float* Wg1 = (const float*)d_in[8];
    const float* bg1 = (const float*)d_in[9];
    const float* Wg2 = (const float*)d_in[10];
    const float* bg2 = (const float*)d_in[11];
    const float* Wp  = (const float*)d_in[12];
    const float* bp  = (const float*)d_in[13];

    float* out  = (float*)d_out;
    float* hout = out + N_LBL;

    float*    h1 = (float*)sym_addr(g_h1);
    float*    h  = (float*)sym_addr(g_h);
    __half2*  xw = (__half2*)sym_addr(g_xw);
    uint32_t* Wh = (uint32_t*)sym_addr(g_Wh);
    uint32_t* Wl = (uint32_t*)sym_addr(g_Wl);

    // --- fork: weight convert on s_w, CSR build on s_prep ---
    cudaEventRecord(ev_fork, 0);
    cudaStreamWaitEvent(s_prep, ev_fork, 0);
    cudaStreamWaitEvent(s_w, ev_fork, 0);

    weight_convert_kernel<<<(WTOTAL + 255) / 256, 256, 0, s_w>>>(W1, W2, Wg1, Wg2);
    cudaEventRecord(ev_w, s_w);

    const int zero_blocks = (N_NODES + 255) / 256;
    prep_kernel<<<zero_blocks + 2, 256, 0, s_prep>>>((const int*)ei, (const int*)eli);
    deg_hist_kernel<<<(N_EDGES / 4 + 255) / 256, 256, 0, s_prep>>>(ei);
    scan_partials_kernel<<<SCAN_BLOCKS, SCAN_TPB, 0, s_prep>>>();
    scan_top_kernel<<<1, 256, 0, s_prep>>>();
    scan_final_kernel<<<SCAN_BLOCKS, SCAN_TPB, 0, s_prep>>>();
    bucket_fill_kernel<<<(N_EDGES + 255) / 256, 256, 0, s_prep>>>(ei);
    cudaEventRecord(ev_join, s_prep);

    const int gy = (N_NODES + 127) / 128;

    // --- preprocess MLP (main stream; GEMM1 gated on weight convert) ---
    cudaStreamWaitEvent(0, ev_w, 0);
    bf16_gemm_kernel<true, true, false><<<dim3(DIM_H1 / 64, gy), 256>>>(
        x, Wh + WOFF_W1, Wl + WOFF_W1, b1, h1, N_NODES, DIM_H1, DIM_IN);
    bf16_gemm_kernel<true, true, false><<<dim3(DIM_H / 64, gy), 256>>>(
        h1, Wh + WOFF_W2, Wl + WOFF_W2, b2, h, N_NODES, DIM_H, DIM_H1);

    const int agg_blocks = (N_NODES + 7) / 8;

    // --- GCN layer 1 ---
    bf16_gemm_kernel<false, false, true><<<dim3(DIM_H / 64, gy), 256>>>(
        h, Wh + WOFF_WG1, Wl + WOFF_WG1, nullptr, xw, N_NODES, DIM_H, DIM_H);
    cudaStreamWaitEvent(0, ev_join, 0);
    gcn_agg_kernel<false><<<agg_blocks, 256>>>(xw, bg1, h, nullptr);

    // --- GCN layer 2 (epilogue also computes head projections) ---
    bf16_gemm_kernel<false, false, true><<<dim3(DIM_H / 64, gy), 256>>>(
        h, Wh + WOFF_WG2, Wl + WOFF_WG2, nullptr, xw, N_NODES, DIM_H, DIM_H);
    gcn_agg_kernel<true><<<agg_blocks, 256>>>(xw, bg2, hout, Wp);

    // --- edge scoring head: one thread per edge ---
    edge_score_kernel<<<(N_LBL + 255) / 256, 256>>>(eli, ea, Wp, bp, out);
}

// round 17
// speedup vs baseline: 1.1332x; 1.0320x over previous
#include <cuda_runtime.h>
#include <cuda_fp16.h>
#include <cstdint>
#include <cstddef>

#define N_NODES 100000
#define N_EDGES 1600000
#define N_LBL   200000
#define DIM_IN  256
#define DIM_H1  128
#define DIM_H   64
#define DIM_EA  8

#define SCAN_TPB    512
#define SCAN_BLOCKS ((N_NODES + SCAN_TPB - 1) / SCAN_TPB)   // 196

// pre-split packed weights: uint32 = bf16x2 (b[2k2] low, b[2k2+1] high)
#define WOFF_W1  0
#define WOFF_W2  16384
#define WOFF_WG1 20480
#define WOFF_WG2 22528
#define WTOTAL   24576

// ---------------- scratch (no allocations allowed) ----------------
__device__ __align__(16) float   g_h1[(size_t)N_NODES * DIM_H1];
__device__ __align__(16) float   g_h [(size_t)N_NODES * DIM_H];
__device__ __align__(16) __half2 g_xw[(size_t)N_NODES * (DIM_H / 2)];
__device__ __align__(16) uint32_t g_Wh[WTOTAL];
__device__ __align__(16) uint32_t g_Wl[WTOTAL];
__device__ float g_pre_s[N_NODES];
__device__ float g_pre_d[N_NODES];
__device__ int   g_perm[N_EDGES];
__device__ int   g_deg[N_NODES];
__device__ int   g_start[N_NODES + 1];
__device__ int   g_cursor[N_NODES];
__device__ int   g_part[SCAN_BLOCKS];
__device__ float g_dinv[N_NODES];
__device__ float g_dinv2[N_NODES];
__device__ int   g_flag[2];

__device__ __forceinline__ float leaky(float v) {
    return v > 0.0f ? v : 0.01f * v;
}

__device__ __forceinline__ void split_pair(float x0, float x1, uint32_t& hi, uint32_t& lo) {
    uint32_t h;
    asm("cvt.rn.bf16x2.f32 %0, %1, %2;" : "=r"(h) : "f"(x1), "f"(x0));
    float h0 = __uint_as_float(h << 16);
    float h1 = __uint_as_float(h & 0xffff0000u);
    float r0 = x0 - h0;
    float r1 = x1 - h1;
    uint32_t l;
    asm("cvt.rn.bf16x2.f32 %0, %1, %2;" : "=r"(l) : "f"(r1), "f"(r0));
    hi = h; lo = l;
}

// ---------------- weight pre-split ----------------
__global__ void weight_convert_kernel(const float* __restrict__ W1,
                                      const float* __restrict__ W2,
                                      const float* __restrict__ Wg1,
                                      const float* __restrict__ Wg2) {
    int idx = blockIdx.x * blockDim.x + threadIdx.x;
    if (idx >= WTOTAL) return;
    const float* W;
    int k2, n, N;
    if (idx < WOFF_W2)        { W = W1;  int i = idx;             N = 128; k2 = i >> 7; n = i & 127; }
    else if (idx < WOFF_WG1)  { W = W2;  int i = idx - WOFF_W2;   N = 64;  k2 = i >> 6; n = i & 63; }
    else if (idx < WOFF_WG2)  { W = Wg1; int i = idx - WOFF_WG1;  N = 64;  k2 = i >> 6; n = i & 63; }
    else                      { W = Wg2; int i = idx - WOFF_WG2;  N = 64;  k2 = i >> 6; n = i & 63; }
    float w0 = W[(size_t)(2 * k2) * N + n];
    float w1 = W[(size_t)(2 * k2 + 1) * N + n];
    uint32_t h, l;
    split_pair(w0, w1, h, l);
    g_Wh[idx] = h;
    g_Wl[idx] = l;
}

// ---------------- prep / CSR build ----------------
__global__ void prep_kernel(const int* __restrict__ ei, const int* __restrict__ eli) {
    int nb = gridDim.x - 2;
    if ((int)blockIdx.x < nb) {
        int i = blockIdx.x * blockDim.x + threadIdx.x;
        if (i < N_NODES) g_deg[i] = 0;
        return;
    }
    const int* p = (blockIdx.x == nb) ? ei : eli;
    int slot = (blockIdx.x == nb) ? 0 : 1;
    __shared__ int anynz;
    if (threadIdx.x == 0) anynz = 0;
    __syncthreads();
    for (int i = threadIdx.x; i < 2048; i += blockDim.x) {
        if (p[2 * i + 1] != 0) anynz = 1;
    }
    __syncthreads();
    if (threadIdx.x == 0) g_flag[slot] = (anynz == 0) ? 1 : 0;
}

__global__ void deg_hist_kernel(const void* __restrict__ raw) {
    int i = blockIdx.x * blockDim.x + threadIdx.x;
    if (i >= N_EDGES / 4) return;
    if (g_flag[0]) {
        const longlong2* p = (const longlong2*)((const long long*)raw + N_EDGES);
        longlong2 a = p[2 * i], b = p[2 * i + 1];
        atomicAdd(&g_deg[(int)a.x], 1);
        atomicAdd(&g_deg[(int)a.y], 1);
        atomicAdd(&g_deg[(int)b.x], 1);
        atomicAdd(&g_deg[(int)b.y], 1);
    } else {
        const int4* p = (const int4*)((const int*)raw + N_EDGES);
        int4 v = p[i];
        atomicAdd(&g_deg[v.x], 1);
        atomicAdd(&g_deg[v.y], 1);
        atomicAdd(&g_deg[v.z], 1);
        atomicAdd(&g_deg[v.w], 1);
    }
}

__global__ void scan_partials_kernel() {
    __shared__ int sh[SCAN_TPB];
    int t = threadIdx.x;
    int i = blockIdx.x * SCAN_TPB + t;
    int v = (i < N_NODES) ? g_deg[i] : 0;
    sh[t] = v;
    __syncthreads();
    for (int off = SCAN_TPB / 2; off > 0; off >>= 1) {
        if (t < off) sh[t] += sh[t + off];
        __syncthreads();
    }
    if (t == 0) g_part[blockIdx.x] = sh[0];
}

__global__ void scan_top_kernel() {
    __shared__ int sh[256];
    int t = threadIdx.x;
    int v = (t < SCAN_BLOCKS) ? g_part[t] : 0;
    sh[t] = v;
    __syncthreads();
    for (int off = 1; off < 256; off <<= 1) {
        int x = (t >= off) ? sh[t - off] : 0;
        __syncthreads();
        sh[t] += x;
        __syncthreads();
    }
    if (t < SCAN_BLOCKS) g_part[t] = sh[t] - v;
}

__global__ void scan_final_kernel() {
    __shared__ int sh[SCAN_TPB];
    int t = threadIdx.x;
    int i = blockIdx.x * SCAN_TPB + t;
    int v = (i < N_NODES) ? g_deg[i] : 0;
    sh[t] = v;
    __syncthreads();
    for (int off = 1; off < SCAN_TPB; off <<= 1) {
        int x = (t >= off) ? sh[t - off] : 0;
        __syncthreads();
        sh[t] += x;
        __syncthreads();
    }
    if (i < N_NODES) {
        int excl = g_part[blockIdx.x] + sh[t] - v;
        g_start[i]  = excl;
        g_cursor[i] = excl;
        float fd = (float)(v + 1);
        g_dinv[i]  = rsqrtf(fd);
        g_dinv2[i] = 1.0f / fd;
    }
    if (i == 0) g_start[N_NODES] = N_EDGES;
}

__global__ void bucket_fill_kernel(const void* __restrict__ raw) {
    int e = blockIdx.x * blockDim.x + threadIdx.x;
    if (e >= N_EDGES) return;
    int r, c;
    if (g_flag[0]) {
        const long long* p = (const long long*)raw;
        r = (int)p[e];
        c = (int)p[N_EDGES + e];
    } else {
        const int* p = (const int*)raw;
        r = p[e];
        c = p[N_EDGES + e];
    }
    int pos = atomicAdd(&g_cursor[c], 1);
    g_perm[pos] = r;
}

// ---------------- mma / cp.async helpers ----------------
__device__ __forceinline__ void mma_bf16(float* acc, const uint32_t* a, const uint32_t* b) {
    asm volatile(
        "mma.sync.aligned.m16n8k16.row.col.f32.bf16.bf16.f32 "
        "{%0,%1,%2,%3}, {%4,%5,%6,%7}, {%8,%9}, {%0,%1,%2,%3};"
        : "+f"(acc[0]), "+f"(acc[1]), "+f"(acc[2]), "+f"(acc[3])
        : "r"(a[0]), "r"(a[1]), "r"(a[2]), "r"(a[3]), "r"(b[0]), "r"(b[1]));
}

__device__ __forceinline__ void cp_async16(uint32_t dst, const void* src, int szbytes) {
    asm volatile("cp.async.cg.shared.global [%0], [%1], 16, %2;"
                 :: "r"(dst), "l"(src), "r"(szbytes));
}

// ---------------- BF16 GEMM (R14/R16-proven), pre-split B --------------------------
template<bool BIAS, bool ACT, bool HALF_OUT>
__global__ __launch_bounds__(256) void bf16_gemm_kernel(
        const float* __restrict__ A,
        const uint32_t* __restrict__ Bh, const uint32_t* __restrict__ Bl,
        const float* __restrict__ bias, void* __restrict__ Cout,
        int M, int N, int K) {
    constexpr int BM = 128, BK = 16;
    constexpr int ASTR = BK + 4;   // 20
    constexpr int BSTR = 64 + 8;   // 72
    __shared__ float    As[2][BM][ASTR];
    __shared__ uint32_t Bhs[2][8][BSTR];
    __shared__ uint32_t Bls[2][8][BSTR];

    const int tid  = threadIdx.x;
    const int warp = tid >> 5, lane = tid & 31;
    const int g    = lane >> 2, tig = lane & 3;
    const int wm0  = (warp & 3) * 32;
    const int wn0  = (warp >> 2) * 32;
    const int row0 = blockIdx.y * BM;
    const int col0 = blockIdx.x * 64;

    const int ar0 = (tid * 4) >> 4,         ac0 = (tid * 4) & 15;
    const int ar1 = ((tid + 256) * 4) >> 4, ac1 = ((tid + 256) * 4) & 15;
    const int bidx = (tid & 127) * 4;
    const int bk2 = bidx >> 6, bnn = bidx & 63;

    const uint32_t as_base  = (uint32_t)__cvta_generic_to_shared(&As[0][0][0]);
    const uint32_t bhs_base = (uint32_t)__cvta_generic_to_shared(&Bhs[0][0][0]);
    const uint32_t bls_base = (uint32_t)__cvta_generic_to_shared(&Bls[0][0][0]);

    float acc[2][4][4];
#pragma unroll
    for (int mt = 0; mt < 2; mt++)
#pragma unroll
        for (int nt = 0; nt < 4; nt++)
#pragma unroll
            for (int i = 0; i < 4; i++) acc[mt][nt][i] = 0.0f;

    auto load_tile = [&](int k0, int st) {
        const float* srcA0 = A + (size_t)(row0 + ar0) * K + k0 + ac0;
        const float* srcA1 = A + (size_t)(row0 + ar1) * K + k0 + ac1;
        int sz0 = (row0 + ar0 < M) ? 16 : 0;
        int sz1 = (row0 + ar1 < M) ? 16 : 0;
        if (!sz0) srcA0 = A;
        if (!sz1) srcA1 = A;
        cp_async16(as_base + ((st * BM + ar0) * ASTR + ac0) * 4, srcA0, sz0);
        cp_async16(as_base + ((st * BM + ar1) * ASTR + ac1) * 4, srcA1, sz1);
        const uint32_t* bsrc = (tid < 128 ? Bh : Bl)
                             + ((size_t)(k0 >> 1) + bk2) * N + col0 + bnn;
        uint32_t bdst = (tid < 128 ? bhs_base : bls_base)
                      + ((st * 8 + bk2) * BSTR + bnn) * 4;
        cp_async16(bdst, bsrc, 16);
        asm volatile("cp.async.commit_group;");
    };

    const int ntiles = K / BK;
    load_tile(0, 0);

    for (int t = 0; t < ntiles; t++) {
        const int st = t & 1;
        if (t + 1 < ntiles) {
            load_tile((t + 1) * BK, st ^ 1);
            asm volatile("cp.async.wait_group 1;");
        } else {
            asm volatile("cp.async.wait_group 0;");
        }
        __syncthreads();

        const int kk = 2 * tig;
        uint32_t ah[2][4], al[2][4];
#pragma unroll
        for (int mt = 0; mt < 2; mt++) {
            int r = wm0 + mt * 16 + g;
            float2 x;
            x = *(const float2*)&As[st][r][kk];
            split_pair(x.x, x.y, ah[mt][0], al[mt][0]);
            x = *(const float2*)&As[st][r + 8][kk];
            split_pair(x.x, x.y, ah[mt][1], al[mt][1]);
            x = *(const float2*)&As[st][r][kk + 8];
            split_pair(x.x, x.y, ah[mt][2], al[mt][2]);
            x = *(const float2*)&As[st][r + 8][kk + 8];
            split_pair(x.x, x.y, ah[mt][3], al[mt][3]);
        }
        uint32_t bh[4][2], bl[4][2];
#pragma unroll
        for (int nt = 0; nt < 4; nt++) {
            int c = wn0 + nt * 8 + g;
            bh[nt][0] = Bhs[st][tig][c];
            bh[nt][1] = Bhs[st][tig + 4][c];
            bl[nt][0] = Bls[st][tig][c];
            bl[nt][1] = Bls[st][tig + 4][c];
        }
#pragma unroll
        for (int mt = 0; mt < 2; mt++)
#pragma unroll
            for (int nt = 0; nt < 4; nt++) {
                mma_bf16(acc[mt][nt], ah[mt], bh[nt]);
                mma_bf16(acc[mt][nt], ah[mt], bl[nt]);
                mma_bf16(acc[mt][nt], al[mt], bh[nt]);
            }
        __syncthreads();
    }

#pragma unroll
    for (int mt = 0; mt < 2; mt++) {
#pragma unroll
        for (int nt = 0; nt < 4; nt++) {
            int r = row0 + wm0 + mt * 16 + g;
            int c = col0 + wn0 + nt * 8 + 2 * tig;
            float b0 = 0.f, b1 = 0.f;
            if (BIAS) { b0 = __ldg(&bias[c]); b1 = __ldg(&bias[c + 1]); }
            if (r < M) {
                float v0 = acc[mt][nt][0] + b0;
                float v1 = acc[mt][nt][1] + b1;
                if (ACT) { v0 = leaky(v0); v1 = leaky(v1); }
                if (HALF_OUT)
                    ((__half2*)Cout)[(size_t)r * (N / 2) + c / 2] = __floats2half2_rn(v0, v1);
                else
                    *(float2*)((float*)Cout + (size_t)r * N + c) = make_float2(v0, v1);
            }
            if (r + 8 < M) {
                float v2 = acc[mt][nt][2] + b0;
                float v3 = acc[mt][nt][3] + b1;
                if (ACT) { v2 = leaky(v2); v3 = leaky(v3); }
                if (HALF_OUT)
                    ((__half2*)Cout)[(size_t)(r + 8) * (N / 2) + c / 2] = __floats2half2_rn(v2, v3);
                else
                    *(float2*)((float*)Cout + (size_t)(r + 8) * N + c) = make_float2(v2, v3);
            }
        }
    }
}

// ---------------- fused GEMM2 + GCN1-GEMM ----------------
// stage 1: h = leaky(h1[M,128] @ W2 + b2)   (N=64 = full width, kept in regs)
// stage 2: xw = h @ Wg1                      (h packed to smem once, K=64)
// smem union (dynamic, 55296 B):
//   stage1: As [2][128][20] f32 @0 (20480), Bhs @20480 (4608), Bls @25088 (4608)
//   stage2: Hh [128][36] u32 @0 (18432), Hl @18432 (18432), W2h [32][72] @36864 (9216), W2l @46080 (9216)
#define FUSE_SMEM 55296

__global__ __launch_bounds__(256) void mlp2_gcn1_kernel(
        const float* __restrict__ A,
        const uint32_t* __restrict__ B1h, const uint32_t* __restrict__ B1l,
        const float* __restrict__ bias,
        const uint32_t* __restrict__ B2h, const uint32_t* __restrict__ B2l,
        __half2* __restrict__ xw, int M) {
    constexpr int BM = 128, BK = 16, K = 128, N = 64;
    constexpr int ASTR = 20, BSTR = 72, HSTR = 36;
    extern __shared__ __align__(16) char sraw[];
    float*    As  = (float*)sraw;                    // [2][128][20]
    uint32_t* Bhs = (uint32_t*)(sraw + 20480);       // [2][8][72]
    uint32_t* Bls = (uint32_t*)(sraw + 25088);
    uint32_t* Hh  = (uint32_t*)sraw;                 // [128][36] (overlays stage1)
    uint32_t* Hl  = (uint32_t*)(sraw + 18432);
    uint32_t* W2h = (uint32_t*)(sraw + 36864);       // [32][72]
    uint32_t* W2l = (uint32_t*)(sraw + 46080);

    const int tid  = threadIdx.x;
    const int warp = tid >> 5, lane = tid & 31;
    const int g    = lane >> 2, tig = lane & 3;
    const int wm0  = (warp & 3) * 32;
    const int wn0  = (warp >> 2) * 32;
    const int row0 = blockIdx.x * BM;

    const int ar0 = (tid * 4) >> 4,         ac0 = (tid * 4) & 15;
    const int ar1 = ((tid + 256) * 4) >> 4, ac1 = ((tid + 256) * 4) & 15;
    const int bidx = (tid & 127) * 4;
    const int bk2 = bidx >> 6, bnn = bidx & 63;

    const uint32_t as_base  = (uint32_t)__cvta_generic_to_shared(As);
    const uint32_t bhs_base = (uint32_t)__cvta_generic_to_shared(Bhs);
    const uint32_t bls_base = (uint32_t)__cvta_generic_to_shared(Bls);

    // preload Wg1 into stage-2 smem (disjoint from stage-1 region)
#pragma unroll
    for (int i = tid; i < 2048; i += 256) {
        int kp = i >> 6, n = i & 63;
        W2h[kp * BSTR + n] = B2h[i];
        W2l[kp * BSTR + n] = B2l[i];
    }

    float acc[2][4][4];
#pragma unroll
    for (int mt = 0; mt < 2; mt++)
#pragma unroll
        for (int nt = 0; nt < 4; nt++)
#pragma unroll
            for (int i = 0; i < 4; i++) acc[mt][nt][i] = 0.0f;

    auto load_tile = [&](int k0, int st) {
        const float* srcA0 = A + (size_t)(row0 + ar0) * K + k0 + ac0;
        const float* srcA1 = A + (size_t)(row0 + ar1) * K + k0 + ac1;
        int sz0 = (row0 + ar0 < M) ? 16 : 0;
        int sz1 = (row0 + ar1 < M) ? 16 : 0;
        if (!sz0) srcA0 = A;
        if (!sz1) srcA1 = A;
        cp_async16(as_base + ((st * BM + ar0) * ASTR + ac0) * 4, srcA0, sz0);
        cp_async16(as_base + ((st * BM + ar1) * ASTR + ac1) * 4, srcA1, sz1);
        const uint32_t* bsrc = (tid < 128 ? B1h : B1l)
                             + ((size_t)(k0 >> 1) + bk2) * N + bnn;
        uint32_t bdst = (tid < 128 ? bhs_base : bls_base)
                      + ((st * 8 + bk2) * BSTR + bnn) * 4;
        cp_async16(bdst, bsrc, 16);
        asm volatile("cp.async.commit_group;");
    };

    const int ntiles = K / BK;   // 8
    load_tile(0, 0);

    for (int t = 0; t < ntiles; t++) {
        const int st = t & 1;
        if (t + 1 < ntiles) {
            load_tile((t + 1) * BK, st ^ 1);
            asm volatile("cp.async.wait_group 1;");
        } else {
            asm volatile("cp.async.wait_group 0;");
        }
        __syncthreads();

        const int kk = 2 * tig;
        uint32_t ah[2][4], al[2][4];
#pragma unroll
        for (int mt = 0; mt < 2; mt++) {
            int r = wm0 + mt * 16 + g;
            float2 x;
            x = *(const float2*)&As[(st * BM + r) * ASTR + kk];
            split_pair(x.x, x.y, ah[mt][0], al[mt][0]);
            x = *(const float2*)&As[(st * BM + r + 8) * ASTR + kk];
            split_pair(x.x, x.y, ah[mt][1], al[mt][1]);
            x = *(const float2*)&As[(st * BM + r) * ASTR + kk + 8];
            split_pair(x.x, x.y, ah[mt][2], al[mt][2]);
            x = *(const float2*)&As[(st * BM + r + 8) * ASTR + kk + 8];
            split_pair(x.x, x.y, ah[mt][3], al[mt][3]);
        }
        uint32_t bh[4][2], bl[4][2];
#pragma unroll
        for (int nt = 0; nt < 4; nt++) {
            int c = wn0 + nt * 8 + g;
            bh[nt][0] = Bhs[(st * 8 + tig) * BSTR + c];
            bh[nt][1] = Bhs[(st * 8 + tig + 4) * BSTR + c];
            bl[nt][0] = Bls[(st * 8 + tig) * BSTR + c];
            bl[nt][1] = Bls[(st * 8 + tig + 4) * BSTR + c];
        }
#pragma unroll
        for (int mt = 0; mt < 2; mt++)
#pragma unroll
            for (int nt = 0; nt < 4; nt++) {
                mma_bf16(acc[mt][nt], ah[mt], bh[nt]);
                mma_bf16(acc[mt][nt], ah[mt], bl[nt]);
                mma_bf16(acc[mt][nt], al[mt], bh[nt]);
            }
        __syncthreads();
    }

    // ---- stage 1 epilogue: bias + leaky, split h into packed smem ----
#pragma unroll
    for (int mt = 0; mt < 2; mt++) {
#pragma unroll
        for (int nt = 0; nt < 4; nt++) {
            int c  = wn0 + nt * 8 + 2 * tig;   // even
            int kp = c >> 1;
            float b0 = __ldg(&bias[c]), b1 = __ldg(&bias[c + 1]);
#pragma unroll
            for (int half = 0; half < 2; half++) {
                int rr = wm0 + mt * 16 + g + half * 8;   // local row
                float v0 = leaky(acc[mt][nt][2 * half + 0] + b0);
                float v1 = leaky(acc[mt][nt][2 * half + 1] + b1);
                uint32_t h, l;
                split_pair(v0, v1, h, l);
                Hh[rr * HSTR + kp] = h;
                Hl[rr * HSTR + kp] = l;
            }
        }
    }
    __syncthreads();

    // ---- stage 2: xw = h @ Wg1, K=64 (4 k-tiles), all smem-resident ----
    float acc2[2][4][4];
#pragma unroll
    for (int mt = 0; mt < 2; mt++)
#pragma unroll
        for (int nt = 0; nt < 4; nt++)
#pragma unroll
            for (int i = 0; i < 4; i++) acc2[mt][nt][i] = 0.0f;

#pragma unroll
    for (int t = 0; t < 4; t++) {
        uint32_t ah[2][4], al[2][4];
#pragma unroll
        for (int mt = 0; mt < 2; mt++) {
            int r = wm0 + mt * 16 + g;
            ah[mt][0] = Hh[r * HSTR + 8 * t + tig];
            ah[mt][1] = Hh[(r + 8) * HSTR + 8 * t + tig];
            ah[mt][2] = Hh[r * HSTR + 8 * t + tig + 4];
            ah[mt][3] = Hh[(r + 8) * HSTR + 8 * t + tig + 4];
            al[mt][0] = Hl[r * HSTR + 8 * t + tig];
            al[mt][1] = Hl[(r + 8) * HSTR + 8 * t + tig];
            al[mt][2] = Hl[r * HSTR + 8 * t + tig + 4];
            al[mt][3] = Hl[(r + 8) * HSTR + 8 * t + tig + 4];
        }
        uint32_t bh[4][2], bl[4][2];
#pragma unroll
        for (int nt = 0; nt < 4; nt++) {
            int c = wn0 + nt * 8 + g;
            bh[nt][0] = W2h[(8 * t + tig) * BSTR + c];
            bh[nt][1] = W2h[(8 * t + tig + 4) * BSTR + c];
            bl[nt][0] = W2l[(8 * t + tig) * BSTR + c];
            bl[nt][1] = W2l[(8 * t + tig + 4) * BSTR + c];
        }
#pragma unroll
        for (int mt = 0; mt < 2; mt++)
#pragma unroll
            for (int nt = 0; nt < 4; nt++) {
                mma_bf16(acc2[mt][nt], ah[mt], bh[nt]);
                mma_bf16(acc2[mt][nt], ah[mt], bl[nt]);
                mma_bf16(acc2[mt][nt], al[mt], bh[nt]);
            }
    }

    // ---- stage 2 epilogue: write xw half2 ----
#pragma unroll
    for (int mt = 0; mt < 2; mt++) {
#pragma unroll
        for (int nt = 0; nt < 4; nt++) {
            int c = wn0 + nt * 8 + 2 * tig;
#pragma unroll
            for (int half = 0; half < 2; half++) {
                int rr = row0 + wm0 + mt * 16 + g + half * 8;
                if (rr >= M) continue;
                float v0 = acc2[mt][nt][2 * half + 0];
                float v1 = acc2[mt][nt][2 * half + 1];
                xw[(size_t)rr * 32 + (c >> 1)] = __floats2half2_rn(v0, v1);
            }
        }
    }
}

// ---------------- fused GCN aggregation: one warp per destination node ----------------
template<bool PROJ>
__global__ __launch_bounds__(256) void gcn_agg_kernel(const __half2* __restrict__ xw,
                                                      const float* __restrict__ bias,
                                                      float* __restrict__ hdst,
                                                      const float* __restrict__ Wp) {
    int node = blockIdx.x * (blockDim.x >> 5) + (threadIdx.x >> 5);
    int lane = threadIdx.x & 31;
    if (node >= N_NODES) return;

    int s   = g_start[node];
    int end = g_start[node + 1];
    float dcol = g_dinv[node];

    float ax = 0.0f, ay = 0.0f;
    int j = s;
    for (; j + 4 <= end; j += 4) {
        int r0 = g_perm[j];
        int r1 = g_perm[j + 1];
        int r2 = g_perm[j + 2];
        int r3 = g_perm[j + 3];
        float w0 = g_dinv[r0] * dcol;
        float w1 = g_dinv[r1] * dcol;
        float w2 = g_dinv[r2] * dcol;
        float w3 = g_dinv[r3] * dcol;
        float2 f0 = __half22float2(xw[(size_t)r0 * 32 + lane]);
        float2 f1 = __half22float2(xw[(size_t)r1 * 32 + lane]);
        float2 f2 = __half22float2(xw[(size_t)r2 * 32 + lane]);
        float2 f3 = __half22float2(xw[(size_t)r3 * 32 + lane]);
        ax = fmaf(w0, f0.x, ax); ay = fmaf(w0, f0.y, ay);
        ax = fmaf(w1, f1.x, ax); ay = fmaf(w1, f1.y, ay);
        ax = fmaf(w2, f2.x, ax); ay = fmaf(w2, f2.y, ay);
        ax = fmaf(w3, f3.x, ax); ay = fmaf(w3, f3.y, ay);
    }
    for (; j < end; j++) {
        int r0 = g_perm[j];
        float w0 = g_dinv[r0] * dcol;
        float2 f0 = __half22float2(xw[(size_t)r0 * 32 + lane]);
        ax = fmaf(w0, f0.x, ax);
        ay = fmaf(w0, f0.y, ay);
    }
    float sw = g_dinv2[node];
    float2 fs = __half22float2(xw[(size_t)node * 32 + lane]);
    ax = fmaf(sw, fs.x, ax);
    ay = fmaf(sw, fs.y, ay);

    ax = leaky(ax + bias[2 * lane]);
    ay = leaky(ay + bias[2 * lane + 1]);
    *(float2*)(hdst + (size_t)node * DIM_H + 2 * lane) = make_float2(ax, ay);

    if (PROJ) {
        float2 ws = *(const float2*)(Wp + 2 * lane);
        float2 wd = *(const float2*)(Wp + DIM_H + 2 * lane);
        float ps = ax * ws.x + ay * ws.y;
        float pd = ax * wd.x + ay * wd.y;
#pragma unroll
        for (int o = 16; o; o >>= 1) {
            ps += __shfl_xor_sync(0xffffffffu, ps, o);
            pd += __shfl_xor_sync(0xffffffffu, pd, o);
        }
        if (lane == 0) {
            g_pre_s[node] = ps;
            g_pre_d[node] = pd;
        }
    }
}

// ---------------- edge scoring head: one THREAD per label edge ----------------
__global__ __launch_bounds__(256) void edge_score_kernel(
        const void* __restrict__ eli, const float* __restrict__ ea,
        const float* __restrict__ Wp, const float* __restrict__ bp,
        float* __restrict__ out) {
    int e = blockIdx.x * blockDim.x + threadIdx.x;
    if (e >= N_LBL) return;
    int s, d;
    if (g_flag[1]) {
        const long long* p = (const long long*)eli;
        s = (int)p[e];
        d = (int)p[N_LBL + e];
    } else {
        const int* p = (const int*)eli;
        s = p[e];
        d = p[N_LBL + e];
    }
    float4 a0 = *(const float4*)(ea + (size_t)e * DIM_EA);
    float4 a1 = *(const float4*)(ea + (size_t)e * DIM_EA + 4);
    float acc = g_pre_s[s] + g_pre_d[d] + __ldg(&bp[0]);
    acc += a0.x * __ldg(&Wp[128]) + a0.y * __ldg(&Wp[129])
         + a0.z * __ldg(&Wp[130]) + a0.w * __ldg(&Wp[131])
         + a1.x * __ldg(&Wp[132]) + a1.y * __ldg(&Wp[133])
         + a1.z * __ldg(&Wp[134]) + a1.w * __ldg(&Wp[135]);
    out[e] = acc;
}

// ---------------- host ----------------
static void* sym_addr(const void* sym) {
    void* p = nullptr;
    cudaGetSymbolAddress(&p, sym);
    return p;
}

extern "C" void kernel_launch(void* const* d_in, const int* in_sizes, int n_in,
                              void* d_out, int out_size) {
    static cudaStream_t s_prep = nullptr, s_w = nullptr;
    static cudaEvent_t ev_fork = nullptr, ev_join = nullptr, ev_w = nullptr;
    if (s_prep == nullptr) {
        cudaStreamCreateWithFlags(&s_prep, cudaStreamNonBlocking);
        cudaStreamCreateWithFlags(&s_w, cudaStreamNonBlocking);
        cudaEventCreateWithFlags(&ev_fork, cudaEventDisableTiming);
        cudaEventCreateWithFlags(&ev_join, cudaEventDisableTiming);
        cudaEventCreateWithFlags(&ev_w, cudaEventDisableTiming);
        cudaFuncSetAttribute(mlp2_gcn1_kernel,
                             cudaFuncAttributeMaxDynamicSharedMemorySize, FUSE_SMEM);
    }

    const float* x   = (const float*)d_in[0];
    const void*  ei  = d_in[1];
    const void*  eli = d_in[2];
    const float* ea  = (const float*)d_in[3];
    const float* W1  = (const float*)d_in[4];
    const float* b1  = (const float*)d_in[5];
    const float* W2  = (const float*)d_in[6];
    const float* b2  = (const float*)d_in[7];
    const float* Wg1 = (const float*)d_in[8];
    const float* bg1 = (const float*)d_in[9];
    const float* Wg2 = (const float*)d_in[10];
    const float* bg2 = (const float*)d_in[11];
    const float* Wp  = (const float*)d_in[12];
    const float* bp  = (const float*)d_in[13];

    float* out  = (float*)d_out;
    float* hout = out + N_LBL;

    float*    h1 = (float*)sym_addr(g_h1);
    float*    h  = (float*)sym_addr(g_h);
    __half2*  xw = (__half2*)sym_addr(g_xw);
    uint32_t* Wh = (uint32_t*)sym_addr(g_Wh);
    uint32_t* Wl = (uint32_t*)sym_addr(g_Wl);

    // --- fork: weight convert on s_w, CSR build on s_prep ---
    cudaEventRecord(ev_fork, 0);
    cudaStreamWaitEvent(s_prep, ev_fork, 0);
    cudaStreamWaitEvent(s_w, ev_fork, 0);

    weight_convert_kernel<<<(WTOTAL + 255) / 256, 256, 0, s_w>>>(W1, W2, Wg1, Wg2);
    cudaEventRecord(ev_w, s_w);

    const int zero_blocks = (N_NODES + 255) / 256;
    prep_kernel<<<zero_blocks + 2, 256, 0, s_prep>>>((const int*)ei, (const int*)eli);
    deg_hist_kernel<<<(N_EDGES / 4 + 255) / 256, 256, 0, s_prep>>>(ei);

    const int gy = (N_NODES + 127) / 128;

    // GEMM1 as 4th host launch (ncu capture window)
    cudaStreamWaitEvent(0, ev_w, 0);
    bf16_gemm_kernel<true, true, false><<<dim3(DIM_H1 / 64, gy), 256>>>(
        x, Wh + WOFF_W1, Wl + WOFF_W1, b1, h1, N_NODES, DIM_H1, DIM_IN);

    scan_partials_kernel<<<SCAN_BLOCKS, SCAN_TPB, 0, s_prep>>>();
    scan_top_kernel<<<1, 256, 0, s_prep>>>();
    scan_final_kernel<<<SCAN_BLOCKS, SCAN_TPB, 0, s_prep>>>();
    bucket_fill_kernel<<<(N_EDGES + 255) / 256, 256, 0, s_prep>>>(ei);
    cudaEventRecord(ev_join, s_prep);

    // --- fused GEMM2 + GCN1-GEMM: h1 -> xw directly ---
    mlp2_gcn1_kernel<<<gy, 256, FUSE_SMEM>>>(
        h1, Wh + WOFF_W2, Wl + WOFF_W2, b2, Wh + WOFF_WG1, Wl + WOFF_WG1, xw, N_NODES);

    const int agg_blocks = (N_NODES + 7) / 8;

    cudaStreamWaitEvent(0, ev_join, 0);
    gcn_agg_kernel<false><<<agg_blocks, 256>>>(xw, bg1, h, nullptr);

    // --- GCN layer 2 ---
    bf16_gemm_kernel<false, false, true><<<dim3(DIM_H / 64, gy), 256>>>(
        h, Wh + WOFF_WG2, Wl + WOFF_WG2, nullptr, xw, N_NODES, DIM_H, DIM_H);
    gcn_agg_kernel<true><<<agg_blocks, 256>>>(xw, bg2, hout, Wp);

    // --- edge scoring head: one thread per edge ---
    edge_score_kernel<<<(N_LBL + 255) / 256, 256>>>(eli, ea, Wp, bp, out);
}